// round 10
// baseline (speedup 1.0000x reference)
#include <cuda_runtime.h>
#include <cuda_bf16.h>
#include <cstdint>

// Problem shape (fixed for this bench)
#define Bdim 128
#define Tdim 784
#define Kdim 512   // K of branch GEMMs
#define Hdim 512   // N of branch GEMMs
#define Odim 10
#define Mdim (Bdim * Tdim)   // 100352

// ---------------------------------------------------------------------------
// Scratch (device globals: allocation inside kernel_launch is forbidden)
// ---------------------------------------------------------------------------
__device__ float    g_d1[(size_t)Mdim * Hdim];
__device__ float    g_d2[(size_t)Mdim * Hdim];
__device__ uint32_t g_ballot[(size_t)Mdim * 16];   // 512 spikes -> 16 words per (b,t)

__device__ __forceinline__ uint32_t smem_addr(const void* p) {
    uint32_t a;
    asm("{ .reg .u64 t; cvta.to.shared.u64 t, %1; cvt.u32.u64 %0, t; }"
        : "=r"(a) : "l"(p));
    return a;
}

// ---------------------------------------------------------------------------
// GEMM kernel: D[branch] = X @ W[branch]^T + b[branch]
//   Bit-exact fp32: each output is an ascending-k chain of scalar IEEE FMAs.
//   grid: (4, 784). x: branch = x>>1, n0 = (x&1)*256. y: m0 = y*128.
//   CTA tile 128(m) x 256(n), per-thread 8x16, K in 32 chunks of BK=16,
//   double-buffered SMEM + double-buffered register fragments.
// ---------------------------------------------------------------------------
#define BK 16
#define LDSX 132                      // floats per Xs k-row (128 data + 4 pad)
#define LDW  260                      // floats per Ws k-row (256 data + 4 pad)
#define XBUF (BK * LDSX)              // 2112 floats per stage
#define WBUF (BK * LDW)               // 4160 floats per stage
#define SMEM_BYTES ((2 * XBUF + 2 * WBUF) * 4)   // 50176 B

__global__ void __launch_bounds__(256, 1) gemm_kernel(
    const float* __restrict__ X,
    const float* __restrict__ W1, const float* __restrict__ b1,
    const float* __restrict__ W2, const float* __restrict__ b2)
{
    extern __shared__ float sm[];
    float* Xs = sm;                   // [2][BK][LDSX]  Xs[k][m] = X[m][k]
    float* Ws = sm + 2 * XBUF;        // [2][BK][LDW]   Ws[k][n] = W[n][k]

    const int tid  = threadIdx.x;
    const int lane = tid & 31;
    const int wid  = tid >> 5;

    // thread tile position within 128x256 CTA tile
    const int mloc = (wid & 3) * 32 + (lane >> 3) * 8;   // 8 rows
    const int nloc = (wid >> 2) * 128 + (lane & 7) * 16; // 16 cols

    const int branch = blockIdx.x >> 1;
    const int n0 = (blockIdx.x & 1) * 256;
    const int m0 = blockIdx.y * 128;

    const float* __restrict__ W    = branch ? W2 : W1;
    const float* __restrict__ bias = branch ? b2 : b1;
    float*       __restrict__ D    = branch ? g_d2 : g_d1;

    // Loader mapping (coalesced): row = tid>>2, col = (tid&3)*4
    const int lrow = tid >> 2;        // 0..63
    const int lcol = (tid & 3) * 4;   // 0,4,8,12
    const float* xg = X + (size_t)(m0 + lrow) * Kdim + lcol;
    const float* wg = W + (size_t)(n0 + lrow) * Kdim + lcol;

    // uint32 SMEM byte addresses (cheaper than 64-bit pointers)
    const uint32_t xs_b = smem_addr(Xs);
    const uint32_t ws_b = smem_addr(Ws);
    const uint32_t xfrag = xs_b + mloc * 4;
    const uint32_t wfrag = ws_b + nloc * 4;

    float acc[8][16];
    #pragma unroll
    for (int i = 0; i < 8; i++)
        #pragma unroll
        for (int j = 0; j < 16; j++) acc[i][j] = 0.f;

    float4 xr[2], wr[4];              // gmem prefetch registers (one chunk)

#define LDG_CHUNK(c) do {                                                   \
        xr[0] = *(const float4*)(xg + (c) * BK);                            \
        xr[1] = *(const float4*)(xg + (size_t)64 * Kdim + (c) * BK);        \
        _Pragma("unroll")                                                   \
        for (int _r = 0; _r < 4; _r++)                                      \
            wr[_r] = *(const float4*)(wg + (size_t)(_r * 64) * Kdim + (c) * BK); \
    } while (0)

#define STS_CHUNK(p) do {                                                   \
        _Pragma("unroll")                                                   \
        for (int _r = 0; _r < 2; _r++) {                                    \
            const float _xv[4] = {xr[_r].x, xr[_r].y, xr[_r].z, xr[_r].w};  \
            _Pragma("unroll")                                               \
            for (int _u = 0; _u < 4; _u++)                                  \
                Xs[(p) * XBUF + (lcol + _u) * LDSX + lrow + _r * 64] = _xv[_u]; \
        }                                                                   \
        _Pragma("unroll")                                                   \
        for (int _r = 0; _r < 4; _r++) {                                    \
            const float _wv[4] = {wr[_r].x, wr[_r].y, wr[_r].z, wr[_r].w};  \
            _Pragma("unroll")                                               \
            for (int _u = 0; _u < 4; _u++)                                  \
                Ws[(p) * WBUF + (lcol + _u) * LDW + lrow + _r * 64] = _wv[_u]; \
        }                                                                   \
    } while (0)

#define LDFRAG(buf, p, kk) do {                                             \
        const uint32_t _xa = xfrag + ((p) * XBUF + (kk) * LDSX) * 4;        \
        const uint32_t _wa = wfrag + ((p) * WBUF + (kk) * LDW) * 4;         \
        asm volatile("ld.shared.v4.f32 {%0,%1,%2,%3}, [%4];"                \
            : "=f"(fa[buf][0]), "=f"(fa[buf][1]), "=f"(fa[buf][2]),         \
              "=f"(fa[buf][3]) : "r"(_xa));                                 \
        asm volatile("ld.shared.v4.f32 {%0,%1,%2,%3}, [%4];"                \
            : "=f"(fa[buf][4]), "=f"(fa[buf][5]), "=f"(fa[buf][6]),         \
              "=f"(fa[buf][7]) : "r"(_xa + 16));                            \
        _Pragma("unroll")                                                   \
        for (int _j = 0; _j < 4; _j++)                                      \
            asm volatile("ld.shared.v4.f32 {%0,%1,%2,%3}, [%4];"            \
                : "=f"(fb[buf][4*_j]), "=f"(fb[buf][4*_j+1]),               \
                  "=f"(fb[buf][4*_j+2]), "=f"(fb[buf][4*_j+3])              \
                : "r"(_wa + _j * 16));                                      \
    } while (0)

    LDG_CHUNK(0);
    STS_CHUNK(0);

    float fa[2][8], fb[2][16];        // fragment double buffer

    for (int c = 0; c < 32; ++c) {
        const int p = c & 1;
        __syncthreads();
        if (c < 31) LDG_CHUNK(c + 1);

        LDFRAG(0, p, 0);
        #pragma unroll
        for (int kk = 0; kk < BK; kk++) {
            const int cur = kk & 1;
            if (kk < BK - 1) LDFRAG(cur ^ 1, p, kk + 1);
            #pragma unroll
            for (int i = 0; i < 8; i++)
                #pragma unroll
                for (int j = 0; j < 16; j++)
                    acc[i][j] = fmaf(fa[cur][i], fb[cur][j], acc[i][j]);
        }

        if (c < 31) STS_CHUNK(p ^ 1);
    }

    // Epilogue: add bias, store 4x float4 per row
    {
        const int nb = n0 + nloc;
        #pragma unroll
        for (int i = 0; i < 8; i++) {
            const int m = m0 + mloc + i;
            float* dst = D + (size_t)m * Hdim + nb;
            #pragma unroll
            for (int j = 0; j < 16; j += 4)
                *(float4*)(dst + j) = make_float4(
                    acc[i][j + 0] + bias[nb + j + 0],
                    acc[i][j + 1] + bias[nb + j + 1],
                    acc[i][j + 2] + bias[nb + j + 2],
                    acc[i][j + 3] + bias[nb + j + 3]);
        }
    }
}

// ---------------------------------------------------------------------------
// Kernel B: sequential LIF scan over T. One thread per (b,h).
// Spikes emitted as warp ballots (32 spikes per uint32) — 6.4 MB total.
// ---------------------------------------------------------------------------
__device__ __forceinline__ float sigmoidf(float x) { return 1.f / (1.f + expf(-x)); }

__global__ void __launch_bounds__(256) scan_kernel(
    const float* __restrict__ tau_m,
    const float* __restrict__ tau_n1,
    const float* __restrict__ tau_n2,
    const float* __restrict__ mem0,
    const float* __restrict__ spike0)
{
    const int tid = blockIdx.x * blockDim.x + threadIdx.x;
    const int b = tid / Hdim;
    const int h = tid - b * Hdim;
    const int lane = threadIdx.x & 31;

    const float alpha = sigmoidf(tau_m[h]);
    const float beta1 = sigmoidf(tau_n1[h]);
    const float beta2 = sigmoidf(tau_n2[h]);
    const float om_a = 1.f - alpha, om_b1 = 1.f - beta1, om_b2 = 1.f - beta2;

    float mem = mem0[tid];
    float spk = spike0[tid];
    float d1 = 0.f, d2 = 0.f;

    size_t base = ((size_t)b * Tdim) * Hdim + h;
    size_t bidx = ((size_t)b * Tdim) * 16 + (h >> 5);   // ballot slot at t=0
    const float* __restrict__ D1 = g_d1;
    const float* __restrict__ D2 = g_d2;

    #pragma unroll 8
    for (int t = 0; t < Tdim; t++) {
        float d1t = __ldcs(D1 + base);
        float d2t = __ldcs(D2 + base);
        d1 = beta1 * d1 + om_b1 * d1t;
        d2 = beta2 * d2 + om_b2 * d2t;
        mem = mem * alpha + om_a * (d1 + d2) - spk;   // V_TH = 1
        spk = (mem > 1.f) ? 1.f : 0.f;
        unsigned bal = __ballot_sync(0xffffffffu, mem > 1.f);
        if (lane == 0) g_ballot[bidx] = bal;
        base += Hdim;
        bidx += 16;
    }
}

// ---------------------------------------------------------------------------
// Kernel C: readout from spike ballots
//   out[m,o] = sum_h bit(m,h) * Wr[o,h] + br[o]
//   Per-lane h-order and shuffle tree identical to the float-spike version
//   -> bit-identical output.
// ---------------------------------------------------------------------------
__global__ void __launch_bounds__(256) readout_kernel(
    const float* __restrict__ Wr,
    const float* __restrict__ br,
    float* __restrict__ Out)
{
    __shared__ float WrS[Odim * Hdim];   // 20 KB
    __shared__ float brS[Odim];
    for (int i = threadIdx.x; i < Odim * Hdim; i += blockDim.x) WrS[i] = Wr[i];
    if (threadIdx.x < Odim) brS[threadIdx.x] = br[threadIdx.x];
    __syncthreads();

    const int warp = threadIdx.x >> 5;
    const int lane = threadIdx.x & 31;
    const int m = blockIdx.x * 8 + warp;

    // one coalesced 64B read: lanes 0..15 hold the 16 ballot words of row m
    const uint32_t* gb = g_ballot + (size_t)m * 16;
    uint32_t w = (lane < 16) ? gb[lane] : 0u;

    float acc[Odim];
    #pragma unroll
    for (int o = 0; o < Odim; o++) acc[o] = 0.f;

    #pragma unroll
    for (int j = 0; j < 16; j++) {               // h = j*32 + lane (ascending)
        const uint32_t wj = __shfl_sync(0xffffffffu, w, j);
        const float s = ((wj >> lane) & 1u) ? 1.f : 0.f;
        const int hh = j * 32 + lane;
        #pragma unroll
        for (int o = 0; o < Odim; o++)
            acc[o] = fmaf(s, WrS[o * Hdim + hh], acc[o]);
    }

    #pragma unroll
    for (int o = 0; o < Odim; o++)
        #pragma unroll
        for (int d = 16; d; d >>= 1)
            acc[o] += __shfl_xor_sync(0xffffffffu, acc[o], d);

    if (lane == 0) {
        #pragma unroll
        for (int o = 0; o < Odim; o++)
            Out[(size_t)m * Odim + o] = acc[o] + brS[o];
    }
}

// ---------------------------------------------------------------------------
// Launch
// ---------------------------------------------------------------------------
extern "C" void kernel_launch(void* const* d_in, const int* in_sizes, int n_in,
                              void* d_out, int out_size)
{
    const float* input_data = (const float*)d_in[0];
    const float* W1     = (const float*)d_in[1];
    const float* b1     = (const float*)d_in[2];
    const float* W2     = (const float*)d_in[3];
    const float* b2     = (const float*)d_in[4];
    const float* tau_m  = (const float*)d_in[5];
    const float* tau_n1 = (const float*)d_in[6];
    const float* tau_n2 = (const float*)d_in[7];
    const float* Wr     = (const float*)d_in[8];
    const float* br     = (const float*)d_in[9];
    const float* mem0   = (const float*)d_in[10];
    const float* spike0 = (const float*)d_in[11];
    float* out = (float*)d_out;

    (void)in_sizes; (void)n_in; (void)out_size;

    cudaFuncSetAttribute(gemm_kernel,
                         cudaFuncAttributeMaxDynamicSharedMemorySize, SMEM_BYTES);

    dim3 ggrid(4, Mdim / 128);   // (branch*2 + n-tile, m-tile)
    gemm_kernel<<<ggrid, 256, SMEM_BYTES>>>(input_data, W1, b1, W2, b2);

    scan_kernel<<<(Bdim * Hdim) / 256, 256>>>(tau_m, tau_n1, tau_n2, mem0, spike0);

    readout_kernel<<<Mdim / 8, 256>>>(Wr, br, out);
}

// round 11
// speedup vs baseline: 2.6196x; 2.6196x over previous
#include <cuda_runtime.h>
#include <cuda_bf16.h>
#include <cstdint>

// Problem shape (fixed for this bench)
#define Bdim 128
#define Tdim 784
#define Kdim 512   // K of branch GEMMs
#define Hdim 512   // N of branch GEMMs
#define Odim 10
#define Mdim (Bdim * Tdim)   // 100352

// ---------------------------------------------------------------------------
// Scratch (device globals: allocation inside kernel_launch is forbidden)
// ---------------------------------------------------------------------------
__device__ float    g_d1[(size_t)Mdim * Hdim];
__device__ float    g_d2[(size_t)Mdim * Hdim];
__device__ uint32_t g_ballot[(size_t)Mdim * 16];   // 512 spikes -> 16 words per (b,t)

// ---------------------------------------------------------------------------
// GEMM kernel (exact R7/R8 shape — measured 2080 us):
//   D[branch] = X @ W[branch]^T + b[branch]
//   Bit-exact fp32: each output is an ascending-k chain of scalar IEEE FMAs.
//   grid: (8, 784). CTA 128x128, BK=16, double-buffered SMEM + register
//   fragment double-buffering. 2 CTAs/SM (128 regs).
// ---------------------------------------------------------------------------
#define BK 16
#define LDSX 132                      // floats per k-row (128 data + 4 pad)
#define XBUF (BK * LDSX)              // floats per stage per matrix
#define SMEM_BYTES (4 * XBUF * 4)     // X[2] + W[2] = 33792 B

__global__ void __launch_bounds__(256, 2) gemm_kernel(
    const float* __restrict__ X,
    const float* __restrict__ W1, const float* __restrict__ b1,
    const float* __restrict__ W2, const float* __restrict__ b2)
{
    extern __shared__ float sm[];
    float* Xs = sm;                   // [2][BK][LDSX]  Xs[k][m] = X[m][k]
    float* Ws = sm + 2 * XBUF;        // [2][BK][LDSX]  Ws[k][n] = W[n][k]

    const int tid  = threadIdx.x;
    const int lane = tid & 31;
    const int wid  = tid >> 5;

    const int mloc = (wid & 3) * 32 + (lane >> 3) * 8;   // thread row base
    const int nloc = (wid >> 2) * 64 + (lane & 7) * 8;   // thread col base

    const int branch = blockIdx.x >> 2;
    const int n0 = (blockIdx.x & 3) * 128;
    const int m0 = blockIdx.y * 128;

    const float* __restrict__ W    = branch ? W2 : W1;
    const float* __restrict__ bias = branch ? b2 : b1;
    float*       __restrict__ D    = branch ? g_d2 : g_d1;

    const int lrow = tid >> 2;
    const int lcol = (tid & 3) * 4;
    const float* xg = X + (size_t)(m0 + lrow) * Kdim + lcol;
    const float* wg = W + (size_t)(n0 + lrow) * Kdim + lcol;

    float acc[8][8];
    #pragma unroll
    for (int i = 0; i < 8; i++)
        #pragma unroll
        for (int j = 0; j < 8; j++) acc[i][j] = 0.f;

    float4 xr[2], wr[2];

#define LDG_CHUNK(c) do {                                                   \
        xr[0] = *(const float4*)(xg + (c) * BK);                            \
        xr[1] = *(const float4*)(xg + (size_t)64 * Kdim + (c) * BK);        \
        wr[0] = *(const float4*)(wg + (c) * BK);                            \
        wr[1] = *(const float4*)(wg + (size_t)64 * Kdim + (c) * BK);        \
    } while (0)

#define STS_CHUNK(p) do {                                                   \
        _Pragma("unroll")                                                   \
        for (int _r = 0; _r < 2; _r++) {                                    \
            const float _xv[4] = {xr[_r].x, xr[_r].y, xr[_r].z, xr[_r].w};  \
            const float _wv[4] = {wr[_r].x, wr[_r].y, wr[_r].z, wr[_r].w};  \
            _Pragma("unroll")                                               \
            for (int _u = 0; _u < 4; _u++) {                                \
                Xs[(p) * XBUF + (lcol + _u) * LDSX + lrow + _r * 64] = _xv[_u]; \
                Ws[(p) * XBUF + (lcol + _u) * LDSX + lrow + _r * 64] = _wv[_u]; \
            }                                                               \
        }                                                                   \
    } while (0)

#define LDFRAG(buf, kk) do {                                                \
        const float* _xr = xb + (kk) * LDSX + mloc;                         \
        const float* _wr = wb + (kk) * LDSX + nloc;                         \
        *(float4*)&fa[buf][0] = *(const float4*)_xr;                        \
        *(float4*)&fa[buf][4] = *(const float4*)(_xr + 4);                  \
        *(float4*)&fb[buf][0] = *(const float4*)_wr;                        \
        *(float4*)&fb[buf][4] = *(const float4*)(_wr + 4);                  \
    } while (0)

    LDG_CHUNK(0);
    STS_CHUNK(0);

    for (int c = 0; c < 32; ++c) {
        const int p = c & 1;
        __syncthreads();
        if (c < 31) LDG_CHUNK(c + 1);

        const float* xb = Xs + p * XBUF;
        const float* wb = Ws + p * XBUF;

        float fa[2][8], fb[2][8];
        LDFRAG(0, 0);
        #pragma unroll
        for (int kk = 0; kk < BK; kk++) {
            const int cur = kk & 1;
            if (kk < BK - 1) LDFRAG(cur ^ 1, kk + 1);
            #pragma unroll
            for (int i = 0; i < 8; i++)
                #pragma unroll
                for (int j = 0; j < 8; j++)
                    acc[i][j] = fmaf(fa[cur][i], fb[cur][j], acc[i][j]);
        }

        if (c < 31) STS_CHUNK(p ^ 1);
    }

    {
        const int nb = n0 + nloc;
        float bsv[8];
        #pragma unroll
        for (int j = 0; j < 8; j++) bsv[j] = bias[nb + j];

        #pragma unroll
        for (int i = 0; i < 8; i++) {
            const int m = m0 + mloc + i;
            float* dst = D + (size_t)m * Hdim + nb;
            *(float4*)dst = make_float4(acc[i][0] + bsv[0], acc[i][1] + bsv[1],
                                        acc[i][2] + bsv[2], acc[i][3] + bsv[3]);
            *(float4*)(dst + 4) = make_float4(acc[i][4] + bsv[4], acc[i][5] + bsv[5],
                                              acc[i][6] + bsv[6], acc[i][7] + bsv[7]);
        }
    }
}

// ---------------------------------------------------------------------------
// Kernel B: sequential LIF scan, software-pipelined in batches of 8 timesteps.
// Loads for batch tb+1 are issued into registers BEFORE the ballots of batch
// tb, so MLP ~16 is sustained across the __ballot_sync scheduling barriers.
// Recurrence statements textually identical to the passing version ->
// identical contraction -> bit-identical spikes.
// ---------------------------------------------------------------------------
__device__ __forceinline__ float sigmoidf(float x) { return 1.f / (1.f + expf(-x)); }

#define SB 8                          // timestep batch (784 = 8*98)

__global__ void __launch_bounds__(256) scan_kernel(
    const float* __restrict__ tau_m,
    const float* __restrict__ tau_n1,
    const float* __restrict__ tau_n2,
    const float* __restrict__ mem0,
    const float* __restrict__ spike0)
{
    const int tid = blockIdx.x * blockDim.x + threadIdx.x;
    const int b = tid / Hdim;
    const int h = tid - b * Hdim;
    const int lane = threadIdx.x & 31;

    const float alpha = sigmoidf(tau_m[h]);
    const float beta1 = sigmoidf(tau_n1[h]);
    const float beta2 = sigmoidf(tau_n2[h]);
    const float om_a = 1.f - alpha, om_b1 = 1.f - beta1, om_b2 = 1.f - beta2;

    float mem = mem0[tid];
    float spk = spike0[tid];
    float d1 = 0.f, d2 = 0.f;

    size_t base = ((size_t)b * Tdim) * Hdim + h;
    size_t bidx = ((size_t)b * Tdim) * 16 + (h >> 5);
    const float* __restrict__ D1 = g_d1;
    const float* __restrict__ D2 = g_d2;

    float pd1[SB], pd2[SB];
    #pragma unroll
    for (int j = 0; j < SB; j++) {
        pd1[j] = __ldcs(D1 + base + (size_t)j * Hdim);
        pd2[j] = __ldcs(D2 + base + (size_t)j * Hdim);
    }

    for (int tb = 0; tb < Tdim / SB; tb++) {
        float nd1[SB], nd2[SB];
        if (tb < Tdim / SB - 1) {
            #pragma unroll
            for (int j = 0; j < SB; j++) {
                nd1[j] = __ldcs(D1 + base + (size_t)(SB + j) * Hdim);
                nd2[j] = __ldcs(D2 + base + (size_t)(SB + j) * Hdim);
            }
        }
        #pragma unroll
        for (int j = 0; j < SB; j++) {
            float d1t = pd1[j];
            float d2t = pd2[j];
            d1 = beta1 * d1 + om_b1 * d1t;
            d2 = beta2 * d2 + om_b2 * d2t;
            mem = mem * alpha + om_a * (d1 + d2) - spk;   // V_TH = 1
            spk = (mem > 1.f) ? 1.f : 0.f;
            unsigned bal = __ballot_sync(0xffffffffu, mem > 1.f);
            if (lane == 0) g_ballot[bidx + (size_t)j * 16] = bal;
        }
        #pragma unroll
        for (int j = 0; j < SB; j++) { pd1[j] = nd1[j]; pd2[j] = nd2[j]; }
        base += (size_t)SB * Hdim;
        bidx += (size_t)SB * 16;
    }
}

// ---------------------------------------------------------------------------
// Kernel C: readout from spike ballots.
//   out[m,o] = sum_h bit(m,h) * Wr[o,h] + br[o]
//   Each warp handles 8 consecutive m rows (amortizes the 20KB Wr staging).
//   Per-row lane h-order and shuffle tree unchanged -> bit-identical output.
// ---------------------------------------------------------------------------
#define ROWS_PER_WARP 8

__global__ void __launch_bounds__(256) readout_kernel(
    const float* __restrict__ Wr,
    const float* __restrict__ br,
    float* __restrict__ Out)
{
    __shared__ float WrS[Odim * Hdim];   // 20 KB
    __shared__ float brS[Odim];
    for (int i = threadIdx.x; i < Odim * Hdim; i += blockDim.x) WrS[i] = Wr[i];
    if (threadIdx.x < Odim) brS[threadIdx.x] = br[threadIdx.x];
    __syncthreads();

    const int warp = threadIdx.x >> 5;
    const int lane = threadIdx.x & 31;
    const int mbase = (blockIdx.x * 8 + warp) * ROWS_PER_WARP;

    for (int g = 0; g < ROWS_PER_WARP; g++) {
        const int m = mbase + g;

        const uint32_t* gb = g_ballot + (size_t)m * 16;
        uint32_t w = (lane < 16) ? gb[lane] : 0u;

        float acc[Odim];
        #pragma unroll
        for (int o = 0; o < Odim; o++) acc[o] = 0.f;

        #pragma unroll
        for (int j = 0; j < 16; j++) {           // h = j*32 + lane (ascending)
            const uint32_t wj = __shfl_sync(0xffffffffu, w, j);
            const float s = ((wj >> lane) & 1u) ? 1.f : 0.f;
            const int hh = j * 32 + lane;
            #pragma unroll
            for (int o = 0; o < Odim; o++)
                acc[o] = fmaf(s, WrS[o * Hdim + hh], acc[o]);
        }

        #pragma unroll
        for (int o = 0; o < Odim; o++)
            #pragma unroll
            for (int d = 16; d; d >>= 1)
                acc[o] += __shfl_xor_sync(0xffffffffu, acc[o], d);

        if (lane == 0) {
            #pragma unroll
            for (int o = 0; o < Odim; o++)
                Out[(size_t)m * Odim + o] = acc[o] + brS[o];
        }
    }
}

// ---------------------------------------------------------------------------
// Launch
// ---------------------------------------------------------------------------
extern "C" void kernel_launch(void* const* d_in, const int* in_sizes, int n_in,
                              void* d_out, int out_size)
{
    const float* input_data = (const float*)d_in[0];
    const float* W1     = (const float*)d_in[1];
    const float* b1     = (const float*)d_in[2];
    const float* W2     = (const float*)d_in[3];
    const float* b2     = (const float*)d_in[4];
    const float* tau_m  = (const float*)d_in[5];
    const float* tau_n1 = (const float*)d_in[6];
    const float* tau_n2 = (const float*)d_in[7];
    const float* Wr     = (const float*)d_in[8];
    const float* br     = (const float*)d_in[9];
    const float* mem0   = (const float*)d_in[10];
    const float* spike0 = (const float*)d_in[11];
    float* out = (float*)d_out;

    (void)in_sizes; (void)n_in; (void)out_size;

    cudaFuncSetAttribute(gemm_kernel,
                         cudaFuncAttributeMaxDynamicSharedMemorySize, SMEM_BYTES);

    dim3 ggrid(8, Mdim / 128);   // (branch*4 + n-tile, m-tile)
    gemm_kernel<<<ggrid, 256, SMEM_BYTES>>>(input_data, W1, b1, W2, b2);

    scan_kernel<<<(Bdim * Hdim) / 256, 256>>>(tau_m, tau_n1, tau_n2, mem0, spike0);

    // Mdim / (8 warps * ROWS_PER_WARP) = 100352 / 64 = 1568 blocks
    readout_kernel<<<Mdim / (8 * ROWS_PER_WARP), 256>>>(Wr, br, out);
}